// round 11
// baseline (speedup 1.0000x reference)
#include <cuda_runtime.h>
#include <math.h>
#include <stdint.h>

// Problem constants (fixed by the dataset)
#define NN 100000       // nodes
#define NE 600000       // edges
// IN = OUT = ED = 128, H = 2, C = 64, MSG = 64, T = 64

typedef unsigned long long ull;

// ---------------------------------------------------------------------------
// Scratch (device globals; no allocation allowed)
// ---------------------------------------------------------------------------
__device__ float    g_q[(size_t)NN * 128];
__device__ float    g_k[(size_t)NN * 128];
__device__ float    g_v[(size_t)NN * 128];
__device__ float    g_e[(size_t)NE * 128];
__device__ float    g_ex[(size_t)NE * 2];
__device__ unsigned g_amax[(size_t)NN * 2];
__device__ float    g_denom[(size_t)NN * 2];

// Pre-packed B fragments for mma.sync.m16n8k16 (row.col, bf16):
// [mat 0..4][term hi/lo][kstep 0..7][ntile 0..15][lane 0..31] -> uint2 {b0,b1}
// mat: 0=Wq 1=Wk 2=Wv 3=Wskip 4=We
__device__ __align__(16) uint2 g_bfrag[5 * 2 * 8 * 16 * 32];

// ---------------------------------------------------------------------------
// Helpers
// ---------------------------------------------------------------------------
__device__ __forceinline__ unsigned smem_u32(const void* p) {
    unsigned a;
    asm("{ .reg .u64 t; cvta.to.shared.u64 t, %1; cvt.u32.u64 %0, t; }"
        : "=r"(a) : "l"(p));
    return a;
}

// fp32 -> bf16 (round-to-nearest-even)
__device__ __forceinline__ unsigned bf16_rn(float x) {
    unsigned u = __float_as_uint(x);
    return (u + 0x7FFFu + ((u >> 16) & 1u)) >> 16;
}
__device__ __forceinline__ void bf16_split(float x, unsigned &hi, unsigned &lo) {
    hi = bf16_rn(x);
    float r = x - __uint_as_float(hi << 16);
    lo = bf16_rn(r);
}
__device__ __forceinline__ void split_pack2(float x0, float x1,
                                            unsigned &ph, unsigned &pl) {
    unsigned h0, l0, h1, l1;
    bf16_split(x0, h0, l0);
    bf16_split(x1, h1, l1);
    ph = h0 | (h1 << 16);
    pl = l0 | (l1 << 16);
}
__device__ __forceinline__ unsigned bf16_term(float x, int term) {
    unsigned h, l;
    bf16_split(x, h, l);
    return term ? l : h;
}

// Total-order float key for unsigned atomicMax
__device__ __forceinline__ unsigned fkey(float f) {
    unsigned u = __float_as_uint(f);
    return (u & 0x80000000u) ? ~u : (u | 0x80000000u);
}
__device__ __forceinline__ float funkey(unsigned k) {
    return (k & 0x80000000u) ? __uint_as_float(k & 0x7fffffffu)
                             : __uint_as_float(~k);
}

// cos(rel_t*w + b): reference's exact fp32 arg, fp32 Cody-Waite 2*pi reduction
__device__ __forceinline__ float cosx(float rt, float w, float b) {
    const float C1 = 6.2831854820251465f;     // float(2*pi)
    const float C2 = -1.7484551e-07f;         // 2*pi - C1
    float arg = __fadd_rn(__fmul_rn(rt, w), b);
    float k = rintf(arg * 0.15915494309189535f);
    float r = fmaf(-k, C1, arg);
    r = fmaf(-k, C2, r);
    return cosf(r);
}

// m16n8k16 bf16 mma, D += A*B (fp32 accum). Stable PTX ISA (sm_80+).
__device__ __forceinline__ void mma16816(float* d, const unsigned* a,
                                         const uint2 b) {
    asm volatile(
        "mma.sync.aligned.m16n8k16.row.col.f32.bf16.bf16.f32 "
        "{%0,%1,%2,%3}, {%4,%5,%6,%7}, {%8,%9}, {%0,%1,%2,%3};"
        : "+f"(d[0]), "+f"(d[1]), "+f"(d[2]), "+f"(d[3])
        : "r"(a[0]), "r"(a[1]), "r"(a[2]), "r"(a[3]), "r"(b.x), "r"(b.y));
}

// ldmatrix x4: loads the full m16k16 bf16 A fragment in one instruction.
// Per-lane address = row (lane&15) of the tile, +16B for lanes 16-31 (k+8).
__device__ __forceinline__ void ldmx4(unsigned* a, unsigned saddr) {
    asm volatile(
        "ldmatrix.sync.aligned.m8n8.x4.shared.b16 {%0,%1,%2,%3}, [%4];"
        : "=r"(a[0]), "=r"(a[1]), "=r"(a[2]), "=r"(a[3]) : "r"(saddr));
}

// ---------------------------------------------------------------------------
// K0: init segment-softmax scratch
// ---------------------------------------------------------------------------
__global__ void init_kernel() {
    int i = blockIdx.x * blockDim.x + threadIdx.x;
    if (i < NN * 2) { g_amax[i] = 0u; g_denom[i] = 0.0f; }
}

// ---------------------------------------------------------------------------
// K-prep: pack all 5 weight matrices into B-fragment order.
// ---------------------------------------------------------------------------
__global__ void prep_w_kernel(const float* __restrict__ Wq,
                              const float* __restrict__ Wk,
                              const float* __restrict__ Wv,
                              const float* __restrict__ Ws,
                              const float* __restrict__ We) {
    int gid = blockIdx.x * 256 + threadIdx.x;     // 5*2*8*16*32 = 40960
    if (gid >= 40960) return;
    int lane = gid & 31;
    int nt   = (gid >> 5) & 15;
    int ks   = (gid >> 9) & 7;
    int term = (gid >> 12) & 1;
    int mat  = gid >> 13;
    const float* W = (mat == 0) ? Wq : (mat == 1) ? Wk : (mat == 2) ? Wv
                   : (mat == 3) ? Ws : We;
    int g  = lane >> 2, tg = lane & 3;
    int n  = nt * 8 + g;
    int k0 = ks * 16 + tg * 2;
    unsigned b0 = bf16_term(W[k0 * 128 + n], term)
                | (bf16_term(W[(k0 + 1) * 128 + n], term) << 16);
    unsigned b1 = bf16_term(W[(k0 + 8) * 128 + n], term)
                | (bf16_term(W[(k0 + 9) * 128 + n], term) << 16);
    g_bfrag[gid] = make_uint2(b0, b1);
}

// ---------------------------------------------------------------------------
// GEMM core.
// A tiles in smem as bf16, row stride 136 elements (272 B): conflict-free
// for both the build stores and the ldmatrix phases (lane row r -> banks
// 4r..4r+3, full coverage per 8-lane phase).
// Warp tiling (8 warps, CTA 128x128): warp w -> rows (w&1)*64, cols (w>>1)*32.
// ---------------------------------------------------------------------------
#define A_STRIDE_W 68                      // u32 words per A row
#define A_STRIDE_B 272                     // bytes per A row
#define A_TILE_B   (128 * 136 * 2)         // 34816 bytes

// 3-term 128x128x128 MMA. aH/aL are per-lane ldmatrix base addresses
// (already offset by mrow0, lane&15 row, and (lane>>4)*16 k-half bytes).
// fragH/fragL are pre-offset by (gnt0*32 + lane).
__device__ __forceinline__ void mma_tile(float acc[4][4][4],
                                         unsigned aH, unsigned aL,
                                         const uint2* __restrict__ fragH,
                                         const uint2* __restrict__ fragL) {
#pragma unroll
    for (int kt = 0; kt < 8; kt++) {
        unsigned ah[4][4], al[4][4];
#pragma unroll
        for (int mt = 0; mt < 4; mt++) {
            ldmx4(ah[mt], aH + mt * (16 * A_STRIDE_B) + kt * 32);
            ldmx4(al[mt], aL + mt * (16 * A_STRIDE_B) + kt * 32);
        }
#pragma unroll
        for (int nt = 0; nt < 4; nt++) {
            uint2 bh = fragH[(kt * 16 + nt) * 32];
            uint2 bl = fragL[(kt * 16 + nt) * 32];
            // term-major issue order: 4 independent HMMAs between
            // dependent writes to the same accumulator
#pragma unroll
            for (int mt = 0; mt < 4; mt++) mma16816(acc[mt][nt], ah[mt], bh);
#pragma unroll
            for (int mt = 0; mt < 4; mt++) mma16816(acc[mt][nt], ah[mt], bl);
#pragma unroll
            for (int mt = 0; mt < 4; mt++) mma16816(acc[mt][nt], al[mt], bh);
        }
    }
}

// ---------------------------------------------------------------------------
// K1: fused node projections (q, k, v, skip). One CTA = 128 node rows;
// A built once, 4 B phases from prepacked fragments.
// ---------------------------------------------------------------------------
#define NODE_OFF_BIAS 0
#define NODE_OFF_AH   2048
#define NODE_OFF_AL   (2048 + A_TILE_B)
#define NODE_SMEM     (2048 + 2 * A_TILE_B)    // 71680

__global__ void __launch_bounds__(256) node_gemm_kernel(
    const float* __restrict__ x,
    const float* __restrict__ bq, const float* __restrict__ bk,
    const float* __restrict__ bv, const float* __restrict__ bs,
    float* __restrict__ out)
{
    extern __shared__ char smem[];
    float*    sBias = (float*)(smem + NODE_OFF_BIAS);
    unsigned* sAh   = (unsigned*)(smem + NODE_OFF_AH);
    unsigned* sAl   = (unsigned*)(smem + NODE_OFF_AL);
    const int tid = threadIdx.x, wid = tid >> 5, lane = tid & 31;

    for (int j = tid; j < 512; j += 256) {
        const float* b = (j < 128) ? bq : (j < 256) ? bk : (j < 384) ? bv : bs;
        sBias[j] = b[j & 127];
    }

    // Build A (hi/lo split of x rows)
    {
        int row = tid >> 1;
        int kh  = (tid & 1) << 6;
        long grow = (long)blockIdx.x * 128 + row;
        bool ok = grow < NN;
        const float4* xr = (const float4*)&x[(size_t)(ok ? grow : 0) * 128 + kh];
#pragma unroll
        for (int c = 0; c < 64; c += 4) {
            float4 v = ok ? xr[c >> 2] : make_float4(0.f, 0.f, 0.f, 0.f);
            int w0 = row * A_STRIDE_W + ((kh + c) >> 1);
            unsigned ph, pl;
            split_pack2(v.x, v.y, ph, pl);
            sAh[w0] = ph;  sAl[w0] = pl;
            split_pack2(v.z, v.w, ph, pl);
            sAh[w0 + 1] = ph;  sAl[w0 + 1] = pl;
        }
    }
    __syncthreads();

    const int mrow0 = (wid & 1) * 64;
    const int ncol0 = (wid >> 1) * 32;
    const int gnt0  = ncol0 >> 3;
    const int g = lane >> 2, tg = lane & 3;

    // per-lane ldmatrix base addresses
    const unsigned laneOff = (unsigned)((mrow0 + (lane & 15)) * A_STRIDE_B
                                        + (lane >> 4) * 16);
    const unsigned aH = smem_u32(sAh) + laneOff;
    const unsigned aL = smem_u32(sAl) + laneOff;

    for (int s = 0; s < 4; s++) {
        float acc[4][4][4];
#pragma unroll
        for (int mt = 0; mt < 4; mt++)
#pragma unroll
            for (int nt = 0; nt < 4; nt++)
#pragma unroll
                for (int r = 0; r < 4; r++) acc[mt][nt][r] = 0.0f;

        const uint2* fragH = &g_bfrag[(size_t)(s * 2 + 0) * 8 * 16 * 32
                                      + gnt0 * 32 + lane];
        const uint2* fragL = &g_bfrag[(size_t)(s * 2 + 1) * 8 * 16 * 32
                                      + gnt0 * 32 + lane];
        mma_tile(acc, aH, aL, fragH, fragL);

        float* dst = (s == 0) ? g_q : (s == 1) ? g_k : (s == 2) ? g_v : out;
#pragma unroll
        for (int mt = 0; mt < 4; mt++) {
            long m0 = (long)blockIdx.x * 128 + mrow0 + mt * 16 + g;
#pragma unroll
            for (int nt = 0; nt < 4; nt++) {
                int col = ncol0 + nt * 8 + tg * 2;
                float b0 = sBias[s * 128 + col];
                float b1 = sBias[s * 128 + col + 1];
                if (m0 < NN) {
                    float2 o = make_float2(acc[mt][nt][0] + b0,
                                           acc[mt][nt][1] + b1);
                    *(float2*)&dst[(size_t)m0 * 128 + col] = o;
                }
                if (m0 + 8 < NN) {
                    float2 o = make_float2(acc[mt][nt][2] + b0,
                                           acc[mt][nt][3] + b1);
                    *(float2*)&dst[(size_t)(m0 + 8) * 128 + col] = o;
                }
            }
        }
    }
}

// ---------------------------------------------------------------------------
// K2: edge GEMM.  A = [cos(rel_t*wt+bt) | msg] built in split form;
// g_e = A @ We with We fragments prepacked (mat 4).
// ---------------------------------------------------------------------------
#define EDGE_OFF_WT  0
#define EDGE_OFF_BT  256
#define EDGE_OFF_AH  512
#define EDGE_OFF_AL  (512 + A_TILE_B)
#define EDGE_SMEM    (512 + 2 * A_TILE_B)      // 70144

__global__ void __launch_bounds__(256) edge_gemm_kernel(
    const int*   __restrict__ ei,
    const float* __restrict__ last_update,
    const float* __restrict__ tv,
    const float* __restrict__ msg,
    const float* __restrict__ wt,
    const float* __restrict__ bt)
{
    extern __shared__ char smem[];
    float*    swt = (float*)(smem + EDGE_OFF_WT);
    float*    sbt = (float*)(smem + EDGE_OFF_BT);
    unsigned* sAh = (unsigned*)(smem + EDGE_OFF_AH);
    unsigned* sAl = (unsigned*)(smem + EDGE_OFF_AL);
    const int tid = threadIdx.x, wid = tid >> 5, lane = tid & 31;

    if (tid < 64)       swt[tid] = wt[tid];
    else if (tid < 128) sbt[tid - 64] = bt[tid - 64];
    __syncthreads();

    // Build A: even threads cos half (cols 0..63), odd threads msg half
    {
        int row = tid >> 1;
        long e = (long)blockIdx.x * 128 + row;
        bool ok = e < NE;
        if ((tid & 1) == 0) {
            float rt = 0.0f;
            if (ok) {
                int s = ei[e];
                rt = last_update[s] - tv[e];
            }
#pragma unroll 8
            for (int c = 0; c < 64; c += 2) {
                float v0 = ok ? cosx(rt, swt[c],     sbt[c])     : 0.0f;
                float v1 = ok ? cosx(rt, swt[c + 1], sbt[c + 1]) : 0.0f;
                unsigned ph, pl;
                split_pack2(v0, v1, ph, pl);
                int w0 = row * A_STRIDE_W + (c >> 1);
                sAh[w0] = ph;  sAl[w0] = pl;
            }
        } else {
            const float4* mr = (const float4*)&msg[(size_t)(ok ? e : 0) * 64];
#pragma unroll
            for (int c = 0; c < 64; c += 4) {
                float4 v = ok ? mr[c >> 2] : make_float4(0.f, 0.f, 0.f, 0.f);
                int w0 = row * A_STRIDE_W + 32 + (c >> 1);
                unsigned ph, pl;
                split_pack2(v.x, v.y, ph, pl);
                sAh[w0] = ph;  sAl[w0] = pl;
                split_pack2(v.z, v.w, ph, pl);
                sAh[w0 + 1] = ph;  sAl[w0 + 1] = pl;
            }
        }
    }
    __syncthreads();

    const int mrow0 = (wid & 1) * 64;
    const int ncol0 = (wid >> 1) * 32;
    const int gnt0  = ncol0 >> 3;
    const int g = lane >> 2, tg = lane & 3;

    const unsigned laneOff = (unsigned)((mrow0 + (lane & 15)) * A_STRIDE_B
                                        + (lane >> 4) * 16);
    const unsigned aH = smem_u32(sAh) + laneOff;
    const unsigned aL = smem_u32(sAl) + laneOff;

    float acc[4][4][4];
#pragma unroll
    for (int mt = 0; mt < 4; mt++)
#pragma unroll
        for (int nt = 0; nt < 4; nt++)
#pragma unroll
            for (int r = 0; r < 4; r++) acc[mt][nt][r] = 0.0f;

    const uint2* fragH = &g_bfrag[(size_t)(4 * 2 + 0) * 8 * 16 * 32
                                  + gnt0 * 32 + lane];
    const uint2* fragL = &g_bfrag[(size_t)(4 * 2 + 1) * 8 * 16 * 32
                                  + gnt0 * 32 + lane];
    mma_tile(acc, aH, aL, fragH, fragL);

#pragma unroll
    for (int mt = 0; mt < 4; mt++) {
        long m0 = (long)blockIdx.x * 128 + mrow0 + mt * 16 + g;
#pragma unroll
        for (int nt = 0; nt < 4; nt++) {
            int col = ncol0 + nt * 8 + tg * 2;
            if (m0 < NE)
                *(float2*)&g_e[(size_t)m0 * 128 + col] =
                    make_float2(acc[mt][nt][0], acc[mt][nt][1]);
            if (m0 + 8 < NE)
                *(float2*)&g_e[(size_t)(m0 + 8) * 128 + col] =
                    make_float2(acc[mt][nt][2], acc[mt][nt][3]);
        }
    }
}

// ---------------------------------------------------------------------------
// K3: per-edge attention logits + segment max (one warp per edge)
// ---------------------------------------------------------------------------
__global__ void __launch_bounds__(256) alpha_kernel(const int* __restrict__ ei)
{
    int edge = blockIdx.x * 8 + (threadIdx.x >> 5);
    int lane = threadIdx.x & 31;
    if (edge >= NE) return;
    int s = ei[edge];
    int d = ei[NE + edge];
    int c = lane * 4;

    float4 qv = *(const float4*)&g_q[(size_t)d * 128 + c];
    float4 kv = *(const float4*)&g_k[(size_t)s * 128 + c];
    float4 ev = *(const float4*)&g_e[(size_t)edge * 128 + c];

    float p = qv.x * (kv.x + ev.x) + qv.y * (kv.y + ev.y)
            + qv.z * (kv.z + ev.z) + qv.w * (kv.w + ev.w);
    p += __shfl_xor_sync(0xffffffffu, p, 8);
    p += __shfl_xor_sync(0xffffffffu, p, 4);
    p += __shfl_xor_sync(0xffffffffu, p, 2);
    p += __shfl_xor_sync(0xffffffffu, p, 1);

    if ((lane & 15) == 0) {
        int h = lane >> 4;
        float alpha = p * 0.125f;
        g_ex[(size_t)edge * 2 + h] = alpha;
        atomicMax(&g_amax[d * 2 + h], fkey(alpha));
    }
}

// ---------------------------------------------------------------------------
// K4: ex = exp(alpha - amax[dst]); segment sum
// ---------------------------------------------------------------------------
__global__ void __launch_bounds__(256) expsum_kernel(const int* __restrict__ ei)
{
    int idx = blockIdx.x * blockDim.x + threadIdx.x;
    if (idx >= NE * 2) return;
    int edge = idx >> 1, h = idx & 1;
    int d = ei[NE + edge];
    float a  = g_ex[idx];
    float mx = funkey(g_amax[d * 2 + h]);
    float ex = expf(a - mx);
    g_ex[idx] = ex;
    atomicAdd(&g_denom[d * 2 + h], ex);
}

// ---------------------------------------------------------------------------
// K5: weighted scatter-add: out[dst] += attn * (v[src] + e)
// ---------------------------------------------------------------------------
__global__ void __launch_bounds__(256) agg_kernel(const int* __restrict__ ei,
                                                  float* __restrict__ out)
{
    int edge = blockIdx.x * 8 + (threadIdx.x >> 5);
    int lane = threadIdx.x & 31;
    if (edge >= NE) return;
    int s = ei[edge];
    int d = ei[NE + edge];
    int h = lane >> 4;

    float ex   = g_ex[(size_t)edge * 2 + h];
    float den  = g_denom[d * 2 + h];
    float attn = ex / (den + 1e-16f);

    int c = lane * 4;
    float4 vv = *(const float4*)&g_v[(size_t)s * 128 + c];
    float4 ev = *(const float4*)&g_e[(size_t)edge * 128 + c];
    float4 r  = make_float4(attn * (vv.x + ev.x), attn * (vv.y + ev.y),
                            attn * (vv.z + ev.z), attn * (vv.w + ev.w));
    float* p = &out[(size_t)d * 128 + c];
    asm volatile("red.global.add.v4.f32 [%0], {%1, %2, %3, %4};"
                 :: "l"(p), "f"(r.x), "f"(r.y), "f"(r.z), "f"(r.w)
                 : "memory");
}

// ---------------------------------------------------------------------------
// kernel_launch
// ---------------------------------------------------------------------------
extern "C" void kernel_launch(void* const* d_in, const int* in_sizes, int n_in,
                              void* d_out, int out_size)
{
    const float* x           = (const float*)d_in[0];
    const float* last_update = (const float*)d_in[1];
    const int*   ei          = (const int*)  d_in[2];
    const float* t           = (const float*)d_in[3];
    const float* msg         = (const float*)d_in[4];
    const float* wt          = (const float*)d_in[5];
    const float* bt          = (const float*)d_in[6];
    const float* Wq          = (const float*)d_in[7];
    const float* bq          = (const float*)d_in[8];
    const float* Wk          = (const float*)d_in[9];
    const float* bk          = (const float*)d_in[10];
    const float* Wv          = (const float*)d_in[11];
    const float* bv          = (const float*)d_in[12];
    const float* We          = (const float*)d_in[13];
    const float* Ws          = (const float*)d_in[14];
    const float* bs          = (const float*)d_in[15];
    float* out = (float*)d_out;

    cudaFuncSetAttribute(node_gemm_kernel,
                         cudaFuncAttributeMaxDynamicSharedMemorySize, NODE_SMEM);
    cudaFuncSetAttribute(edge_gemm_kernel,
                         cudaFuncAttributeMaxDynamicSharedMemorySize, EDGE_SMEM);

    init_kernel<<<(NN * 2 + 255) / 256, 256>>>();
    prep_w_kernel<<<(40960 + 255) / 256, 256>>>(Wq, Wk, Wv, Ws, We);

    node_gemm_kernel<<<(NN + 127) / 128, 256, NODE_SMEM>>>(
        x, bq, bk, bv, bs, out);

    edge_gemm_kernel<<<(NE + 127) / 128, 256, EDGE_SMEM>>>(
        ei, last_update, t, msg, wt, bt);

    alpha_kernel<<<(NE + 7) / 8, 256>>>(ei);
    expsum_kernel<<<(NE * 2 + 255) / 256, 256>>>(ei);
    agg_kernel<<<(NE + 7) / 8, 256>>>(ei, out);
}

// round 12
// speedup vs baseline: 1.2549x; 1.2549x over previous
#include <cuda_runtime.h>
#include <math.h>
#include <stdint.h>

// Problem constants (fixed by the dataset)
#define NN 100000       // nodes
#define NE 600000       // edges
// IN = OUT = ED = 128, H = 2, C = 64, MSG = 64, T = 64

typedef unsigned long long ull;

// ---------------------------------------------------------------------------
// Scratch (device globals; no allocation allowed)
// ---------------------------------------------------------------------------
__device__ float    g_q[(size_t)NN * 128];
__device__ float    g_k[(size_t)NN * 128];
__device__ float    g_v[(size_t)NN * 128];
__device__ float    g_e[(size_t)NE * 128];
__device__ float    g_ex[(size_t)NE * 2];
__device__ unsigned g_amax[(size_t)NN * 2];
__device__ float    g_denom[(size_t)NN * 2];

// Pre-packed B fragments for mma.sync.m16n8k16 (row.col, bf16):
// [mat 0..4][term hi/lo][kstep 0..7][ntile 0..15][lane 0..31] -> uint2 {b0,b1}
// mat: 0=Wq 1=Wk 2=Wv 3=Wskip 4=We
__device__ __align__(16) uint2 g_bfrag[5 * 2 * 8 * 16 * 32];

// ---------------------------------------------------------------------------
// Helpers
// ---------------------------------------------------------------------------
__device__ __forceinline__ unsigned smem_u32(const void* p) {
    unsigned a;
    asm("{ .reg .u64 t; cvta.to.shared.u64 t, %1; cvt.u32.u64 %0, t; }"
        : "=r"(a) : "l"(p));
    return a;
}

// fp32 -> bf16 (round-to-nearest-even)
__device__ __forceinline__ unsigned bf16_rn(float x) {
    unsigned u = __float_as_uint(x);
    return (u + 0x7FFFu + ((u >> 16) & 1u)) >> 16;
}
__device__ __forceinline__ void bf16_split(float x, unsigned &hi, unsigned &lo) {
    hi = bf16_rn(x);
    float r = x - __uint_as_float(hi << 16);
    lo = bf16_rn(r);
}
__device__ __forceinline__ void split_pack2(float x0, float x1,
                                            unsigned &ph, unsigned &pl) {
    unsigned h0, l0, h1, l1;
    bf16_split(x0, h0, l0);
    bf16_split(x1, h1, l1);
    ph = h0 | (h1 << 16);
    pl = l0 | (l1 << 16);
}
__device__ __forceinline__ unsigned bf16_term(float x, int term) {
    unsigned h, l;
    bf16_split(x, h, l);
    return term ? l : h;
}

// Total-order float key for unsigned atomicMax
__device__ __forceinline__ unsigned fkey(float f) {
    unsigned u = __float_as_uint(f);
    return (u & 0x80000000u) ? ~u : (u | 0x80000000u);
}
__device__ __forceinline__ float funkey(unsigned k) {
    return (k & 0x80000000u) ? __uint_as_float(k & 0x7fffffffu)
                             : __uint_as_float(~k);
}

// cos(rel_t*w + b): reference's exact fp32 arg, fp32 Cody-Waite 2*pi reduction
__device__ __forceinline__ float cosx(float rt, float w, float b) {
    const float C1 = 6.2831854820251465f;     // float(2*pi)
    const float C2 = -1.7484551e-07f;         // 2*pi - C1
    float arg = __fadd_rn(__fmul_rn(rt, w), b);
    float k = rintf(arg * 0.15915494309189535f);
    float r = fmaf(-k, C1, arg);
    r = fmaf(-k, C2, r);
    return cosf(r);
}

// m16n8k16 bf16 mma, D += A*B (fp32 accum). Stable PTX ISA (sm_80+).
__device__ __forceinline__ void mma16816(float* d, const unsigned* a,
                                         const uint2 b) {
    asm volatile(
        "mma.sync.aligned.m16n8k16.row.col.f32.bf16.bf16.f32 "
        "{%0,%1,%2,%3}, {%4,%5,%6,%7}, {%8,%9}, {%0,%1,%2,%3};"
        : "+f"(d[0]), "+f"(d[1]), "+f"(d[2]), "+f"(d[3])
        : "r"(a[0]), "r"(a[1]), "r"(a[2]), "r"(a[3]), "r"(b.x), "r"(b.y));
}

// ldmatrix x4: loads the full m16k16 bf16 A fragment in one instruction.
// Per-lane address = row (lane&15) of the tile, +16B for lanes 16-31 (k+8).
__device__ __forceinline__ void ldmx4(unsigned* a, unsigned saddr) {
    asm volatile(
        "ldmatrix.sync.aligned.m8n8.x4.shared.b16 {%0,%1,%2,%3}, [%4];"
        : "=r"(a[0]), "=r"(a[1]), "=r"(a[2]), "=r"(a[3]) : "r"(saddr));
}

// ---------------------------------------------------------------------------
// K0: init segment-softmax scratch
// ---------------------------------------------------------------------------
__global__ void init_kernel() {
    int i = blockIdx.x * blockDim.x + threadIdx.x;
    if (i < NN * 2) { g_amax[i] = 0u; g_denom[i] = 0.0f; }
}

// ---------------------------------------------------------------------------
// K-prep: pack all 5 weight matrices into B-fragment order.
// ---------------------------------------------------------------------------
__global__ void prep_w_kernel(const float* __restrict__ Wq,
                              const float* __restrict__ Wk,
                              const float* __restrict__ Wv,
                              const float* __restrict__ Ws,
                              const float* __restrict__ We) {
    int gid = blockIdx.x * 256 + threadIdx.x;     // 5*2*8*16*32 = 40960
    if (gid >= 40960) return;
    int lane = gid & 31;
    int nt   = (gid >> 5) & 15;
    int ks   = (gid >> 9) & 7;
    int term = (gid >> 12) & 1;
    int mat  = gid >> 13;
    const float* W = (mat == 0) ? Wq : (mat == 1) ? Wk : (mat == 2) ? Wv
                   : (mat == 3) ? Ws : We;
    int g  = lane >> 2, tg = lane & 3;
    int n  = nt * 8 + g;
    int k0 = ks * 16 + tg * 2;
    unsigned b0 = bf16_term(W[k0 * 128 + n], term)
                | (bf16_term(W[(k0 + 1) * 128 + n], term) << 16);
    unsigned b1 = bf16_term(W[(k0 + 8) * 128 + n], term)
                | (bf16_term(W[(k0 + 9) * 128 + n], term) << 16);
    g_bfrag[gid] = make_uint2(b0, b1);
}

// ---------------------------------------------------------------------------
// GEMM core.
// A tiles in smem as bf16, row stride 136 elements (272 B): conflict-free
// for both the build stores and the ldmatrix phases (lane row r -> banks
// 4r..4r+3, full coverage per 8-lane phase).
// Warp tiling (8 warps, CTA 128x128): warp w -> rows (w&1)*64, cols (w>>1)*32.
// ---------------------------------------------------------------------------
#define A_STRIDE_W 68                      // u32 words per A row
#define A_STRIDE_B 272                     // bytes per A row
#define A_TILE_B   (128 * 136 * 2)         // 34816 bytes

// 3-term 128x128x128 MMA. aH/aL are per-lane ldmatrix base addresses
// (already offset by mrow0, lane&15 row, and (lane>>4)*16 k-half bytes).
// fragH/fragL are pre-offset by (gnt0*32 + lane).
__device__ __forceinline__ void mma_tile(float acc[4][4][4],
                                         unsigned aH, unsigned aL,
                                         const uint2* __restrict__ fragH,
                                         const uint2* __restrict__ fragL) {
#pragma unroll
    for (int kt = 0; kt < 8; kt++) {
        unsigned ah[4][4], al[4][4];
#pragma unroll
        for (int mt = 0; mt < 4; mt++) {
            ldmx4(ah[mt], aH + mt * (16 * A_STRIDE_B) + kt * 32);
            ldmx4(al[mt], aL + mt * (16 * A_STRIDE_B) + kt * 32);
        }
#pragma unroll
        for (int nt = 0; nt < 4; nt++) {
            uint2 bh = fragH[(kt * 16 + nt) * 32];
            uint2 bl = fragL[(kt * 16 + nt) * 32];
            // term-major issue order: 4 independent HMMAs between
            // dependent writes to the same accumulator
#pragma unroll
            for (int mt = 0; mt < 4; mt++) mma16816(acc[mt][nt], ah[mt], bh);
#pragma unroll
            for (int mt = 0; mt < 4; mt++) mma16816(acc[mt][nt], ah[mt], bl);
#pragma unroll
            for (int mt = 0; mt < 4; mt++) mma16816(acc[mt][nt], al[mt], bh);
        }
    }
}

// ---------------------------------------------------------------------------
// K1: fused node projections (q, k, v, skip). One CTA = 128 node rows;
// A built once, 4 B phases from prepacked fragments.
// __launch_bounds__(256, 2): cap regs at 128 so 2 CTAs/SM fit (the R11
// regression was regs=130 -> 1 CTA/SM -> occupancy collapse).
// ---------------------------------------------------------------------------
#define NODE_OFF_BIAS 0
#define NODE_OFF_AH   2048
#define NODE_OFF_AL   (2048 + A_TILE_B)
#define NODE_SMEM     (2048 + 2 * A_TILE_B)    // 71680

__global__ void __launch_bounds__(256, 2) node_gemm_kernel(
    const float* __restrict__ x,
    const float* __restrict__ bq, const float* __restrict__ bk,
    const float* __restrict__ bv, const float* __restrict__ bs,
    float* __restrict__ out)
{
    extern __shared__ char smem[];
    float*    sBias = (float*)(smem + NODE_OFF_BIAS);
    unsigned* sAh   = (unsigned*)(smem + NODE_OFF_AH);
    unsigned* sAl   = (unsigned*)(smem + NODE_OFF_AL);
    const int tid = threadIdx.x, wid = tid >> 5, lane = tid & 31;

    for (int j = tid; j < 512; j += 256) {
        const float* b = (j < 128) ? bq : (j < 256) ? bk : (j < 384) ? bv : bs;
        sBias[j] = b[j & 127];
    }

    // Build A (hi/lo split of x rows)
    {
        int row = tid >> 1;
        int kh  = (tid & 1) << 6;
        long grow = (long)blockIdx.x * 128 + row;
        bool ok = grow < NN;
        const float4* xr = (const float4*)&x[(size_t)(ok ? grow : 0) * 128 + kh];
#pragma unroll
        for (int c = 0; c < 64; c += 4) {
            float4 v = ok ? xr[c >> 2] : make_float4(0.f, 0.f, 0.f, 0.f);
            int w0 = row * A_STRIDE_W + ((kh + c) >> 1);
            unsigned ph, pl;
            split_pack2(v.x, v.y, ph, pl);
            sAh[w0] = ph;  sAl[w0] = pl;
            split_pack2(v.z, v.w, ph, pl);
            sAh[w0 + 1] = ph;  sAl[w0 + 1] = pl;
        }
    }
    __syncthreads();

    const int mrow0 = (wid & 1) * 64;
    const int ncol0 = (wid >> 1) * 32;
    const int gnt0  = ncol0 >> 3;
    const int g = lane >> 2, tg = lane & 3;

    // per-lane ldmatrix base addresses
    const unsigned laneOff = (unsigned)((mrow0 + (lane & 15)) * A_STRIDE_B
                                        + (lane >> 4) * 16);
    const unsigned aH = smem_u32(sAh) + laneOff;
    const unsigned aL = smem_u32(sAl) + laneOff;

    for (int s = 0; s < 4; s++) {
        float acc[4][4][4];
#pragma unroll
        for (int mt = 0; mt < 4; mt++)
#pragma unroll
            for (int nt = 0; nt < 4; nt++)
#pragma unroll
                for (int r = 0; r < 4; r++) acc[mt][nt][r] = 0.0f;

        const uint2* fragH = &g_bfrag[(size_t)(s * 2 + 0) * 8 * 16 * 32
                                      + gnt0 * 32 + lane];
        const uint2* fragL = &g_bfrag[(size_t)(s * 2 + 1) * 8 * 16 * 32
                                      + gnt0 * 32 + lane];
        mma_tile(acc, aH, aL, fragH, fragL);

        float* dst = (s == 0) ? g_q : (s == 1) ? g_k : (s == 2) ? g_v : out;
#pragma unroll
        for (int mt = 0; mt < 4; mt++) {
            long m0 = (long)blockIdx.x * 128 + mrow0 + mt * 16 + g;
#pragma unroll
            for (int nt = 0; nt < 4; nt++) {
                int col = ncol0 + nt * 8 + tg * 2;
                float b0 = sBias[s * 128 + col];
                float b1 = sBias[s * 128 + col + 1];
                if (m0 < NN) {
                    float2 o = make_float2(acc[mt][nt][0] + b0,
                                           acc[mt][nt][1] + b1);
                    *(float2*)&dst[(size_t)m0 * 128 + col] = o;
                }
                if (m0 + 8 < NN) {
                    float2 o = make_float2(acc[mt][nt][2] + b0,
                                           acc[mt][nt][3] + b1);
                    *(float2*)&dst[(size_t)(m0 + 8) * 128 + col] = o;
                }
            }
        }
    }
}

// ---------------------------------------------------------------------------
// K2: edge GEMM.  A = [cos(rel_t*wt+bt) | msg] built in split form;
// g_e = A @ We with We fragments prepacked (mat 4).
// ---------------------------------------------------------------------------
#define EDGE_OFF_WT  0
#define EDGE_OFF_BT  256
#define EDGE_OFF_AH  512
#define EDGE_OFF_AL  (512 + A_TILE_B)
#define EDGE_SMEM    (512 + 2 * A_TILE_B)      // 70144

__global__ void __launch_bounds__(256, 2) edge_gemm_kernel(
    const int*   __restrict__ ei,
    const float* __restrict__ last_update,
    const float* __restrict__ tv,
    const float* __restrict__ msg,
    const float* __restrict__ wt,
    const float* __restrict__ bt)
{
    extern __shared__ char smem[];
    float*    swt = (float*)(smem + EDGE_OFF_WT);
    float*    sbt = (float*)(smem + EDGE_OFF_BT);
    unsigned* sAh = (unsigned*)(smem + EDGE_OFF_AH);
    unsigned* sAl = (unsigned*)(smem + EDGE_OFF_AL);
    const int tid = threadIdx.x, wid = tid >> 5, lane = tid & 31;

    if (tid < 64)       swt[tid] = wt[tid];
    else if (tid < 128) sbt[tid - 64] = bt[tid - 64];
    __syncthreads();

    // Build A: even threads cos half (cols 0..63), odd threads msg half
    {
        int row = tid >> 1;
        long e = (long)blockIdx.x * 128 + row;
        bool ok = e < NE;
        if ((tid & 1) == 0) {
            float rt = 0.0f;
            if (ok) {
                int s = ei[e];
                rt = last_update[s] - tv[e];
            }
#pragma unroll 8
            for (int c = 0; c < 64; c += 2) {
                float v0 = ok ? cosx(rt, swt[c],     sbt[c])     : 0.0f;
                float v1 = ok ? cosx(rt, swt[c + 1], sbt[c + 1]) : 0.0f;
                unsigned ph, pl;
                split_pack2(v0, v1, ph, pl);
                int w0 = row * A_STRIDE_W + (c >> 1);
                sAh[w0] = ph;  sAl[w0] = pl;
            }
        } else {
            const float4* mr = (const float4*)&msg[(size_t)(ok ? e : 0) * 64];
#pragma unroll
            for (int c = 0; c < 64; c += 4) {
                float4 v = ok ? mr[c >> 2] : make_float4(0.f, 0.f, 0.f, 0.f);
                int w0 = row * A_STRIDE_W + 32 + (c >> 1);
                unsigned ph, pl;
                split_pack2(v.x, v.y, ph, pl);
                sAh[w0] = ph;  sAl[w0] = pl;
                split_pack2(v.z, v.w, ph, pl);
                sAh[w0 + 1] = ph;  sAl[w0 + 1] = pl;
            }
        }
    }
    __syncthreads();

    const int mrow0 = (wid & 1) * 64;
    const int ncol0 = (wid >> 1) * 32;
    const int gnt0  = ncol0 >> 3;
    const int g = lane >> 2, tg = lane & 3;

    const unsigned laneOff = (unsigned)((mrow0 + (lane & 15)) * A_STRIDE_B
                                        + (lane >> 4) * 16);
    const unsigned aH = smem_u32(sAh) + laneOff;
    const unsigned aL = smem_u32(sAl) + laneOff;

    float acc[4][4][4];
#pragma unroll
    for (int mt = 0; mt < 4; mt++)
#pragma unroll
        for (int nt = 0; nt < 4; nt++)
#pragma unroll
            for (int r = 0; r < 4; r++) acc[mt][nt][r] = 0.0f;

    const uint2* fragH = &g_bfrag[(size_t)(4 * 2 + 0) * 8 * 16 * 32
                                  + gnt0 * 32 + lane];
    const uint2* fragL = &g_bfrag[(size_t)(4 * 2 + 1) * 8 * 16 * 32
                                  + gnt0 * 32 + lane];
    mma_tile(acc, aH, aL, fragH, fragL);

#pragma unroll
    for (int mt = 0; mt < 4; mt++) {
        long m0 = (long)blockIdx.x * 128 + mrow0 + mt * 16 + g;
#pragma unroll
        for (int nt = 0; nt < 4; nt++) {
            int col = ncol0 + nt * 8 + tg * 2;
            if (m0 < NE)
                *(float2*)&g_e[(size_t)m0 * 128 + col] =
                    make_float2(acc[mt][nt][0], acc[mt][nt][1]);
            if (m0 + 8 < NE)
                *(float2*)&g_e[(size_t)(m0 + 8) * 128 + col] =
                    make_float2(acc[mt][nt][2], acc[mt][nt][3]);
        }
    }
}

// ---------------------------------------------------------------------------
// K3: per-edge attention logits + segment max (one warp per edge)
// ---------------------------------------------------------------------------
__global__ void __launch_bounds__(256) alpha_kernel(const int* __restrict__ ei)
{
    int edge = blockIdx.x * 8 + (threadIdx.x >> 5);
    int lane = threadIdx.x & 31;
    if (edge >= NE) return;
    int s = ei[edge];
    int d = ei[NE + edge];
    int c = lane * 4;

    float4 qv = *(const float4*)&g_q[(size_t)d * 128 + c];
    float4 kv = *(const float4*)&g_k[(size_t)s * 128 + c];
    float4 ev = *(const float4*)&g_e[(size_t)edge * 128 + c];

    float p = qv.x * (kv.x + ev.x) + qv.y * (kv.y + ev.y)
            + qv.z * (kv.z + ev.z) + qv.w * (kv.w + ev.w);
    p += __shfl_xor_sync(0xffffffffu, p, 8);
    p += __shfl_xor_sync(0xffffffffu, p, 4);
    p += __shfl_xor_sync(0xffffffffu, p, 2);
    p += __shfl_xor_sync(0xffffffffu, p, 1);

    if ((lane & 15) == 0) {
        int h = lane >> 4;
        float alpha = p * 0.125f;
        g_ex[(size_t)edge * 2 + h] = alpha;
        atomicMax(&g_amax[d * 2 + h], fkey(alpha));
    }
}

// ---------------------------------------------------------------------------
// K4: ex = exp(alpha - amax[dst]); segment sum
// ---------------------------------------------------------------------------
__global__ void __launch_bounds__(256) expsum_kernel(const int* __restrict__ ei)
{
    int idx = blockIdx.x * blockDim.x + threadIdx.x;
    if (idx >= NE * 2) return;
    int edge = idx >> 1, h = idx & 1;
    int d = ei[NE + edge];
    float a  = g_ex[idx];
    float mx = funkey(g_amax[d * 2 + h]);
    float ex = expf(a - mx);
    g_ex[idx] = ex;
    atomicAdd(&g_denom[d * 2 + h], ex);
}

// ---------------------------------------------------------------------------
// K5: weighted scatter-add: out[dst] += attn * (v[src] + e)
// ---------------------------------------------------------------------------
__global__ void __launch_bounds__(256) agg_kernel(const int* __restrict__ ei,
                                                  float* __restrict__ out)
{
    int edge = blockIdx.x * 8 + (threadIdx.x >> 5);
    int lane = threadIdx.x & 31;
    if (edge >= NE) return;
    int s = ei[edge];
    int d = ei[NE + edge];
    int h = lane >> 4;

    float ex   = g_ex[(size_t)edge * 2 + h];
    float den  = g_denom[d * 2 + h];
    float attn = ex / (den + 1e-16f);

    int c = lane * 4;
    float4 vv = *(const float4*)&g_v[(size_t)s * 128 + c];
    float4 ev = *(const float4*)&g_e[(size_t)edge * 128 + c];
    float4 r  = make_float4(attn * (vv.x + ev.x), attn * (vv.y + ev.y),
                            attn * (vv.z + ev.z), attn * (vv.w + ev.w));
    float* p = &out[(size_t)d * 128 + c];
    asm volatile("red.global.add.v4.f32 [%0], {%1, %2, %3, %4};"
                 :: "l"(p), "f"(r.x), "f"(r.y), "f"(r.z), "f"(r.w)
                 : "memory");
}

// ---------------------------------------------------------------------------
// kernel_launch
// ---------------------------------------------------------------------------
extern "C" void kernel_launch(void* const* d_in, const int* in_sizes, int n_in,
                              void* d_out, int out_size)
{
    const float* x           = (const float*)d_in[0];
    const float* last_update = (const float*)d_in[1];
    const int*   ei          = (const int*)  d_in[2];
    const float* t           = (const float*)d_in[3];
    const float* msg         = (const float*)d_in[4];
    const float* wt          = (const float*)d_in[5];
    const float* bt          = (const float*)d_in[6];
    const float* Wq          = (const float*)d_in[7];
    const float* bq          = (const float*)d_in[8];
    const float* Wk          = (const float*)d_in[9];
    const float* bk          = (const float*)d_in[10];
    const float* Wv          = (const float*)d_in[11];
    const float* bv          = (const float*)d_in[12];
    const float* We          = (const float*)d_in[13];
    const float* Ws          = (const float*)d_in[14];
    const float* bs          = (const float*)d_in[15];
    float* out = (float*)d_out;

    cudaFuncSetAttribute(node_gemm_kernel,
                         cudaFuncAttributeMaxDynamicSharedMemorySize, NODE_SMEM);
    cudaFuncSetAttribute(edge_gemm_kernel,
                         cudaFuncAttributeMaxDynamicSharedMemorySize, EDGE_SMEM);

    init_kernel<<<(NN * 2 + 255) / 256, 256>>>();
    prep_w_kernel<<<(40960 + 255) / 256, 256>>>(Wq, Wk, Wv, Ws, We);

    node_gemm_kernel<<<(NN + 127) / 128, 256, NODE_SMEM>>>(
        x, bq, bk, bv, bs, out);

    edge_gemm_kernel<<<(NE + 127) / 128, 256, EDGE_SMEM>>>(
        ei, last_update, t, msg, wt, bt);

    alpha_kernel<<<(NE + 7) / 8, 256>>>(ei);
    expsum_kernel<<<(NE * 2 + 255) / 256, 256>>>(ei);
    agg_kernel<<<(NE + 7) / 8, 256>>>(ei, out);
}